// round 17
// baseline (speedup 1.0000x reference)
#include <cuda_runtime.h>
#include <cstdint>

#define NUM_DENSE 13
#define NUM_SPARSE 26
#define FEAT_NUM 40000
#define FLE 1040013                        // feature length (elements)
#define BATCH 4096
#define NGROUP 6
#define ROWS 16                            // batch rows per work unit
#define UNITS_PER_GROUP (BATCH / ROWS)     // 256
#define TOTAL_UNITS (NGROUP * UNITS_PER_GROUP)  // 1536
#define GRID_GATHER 444                    // 3 persistent CTAs per SM

// Slot-group boundaries {5,5,4,4,4,4}: bands 51/51/41/41/41/41 MB.
__constant__ int c_GS[NGROUP + 1] = {0, 5, 10, 14, 18, 22, 26};

// Accumulators: zero-init at load; fm_final re-zeroes after reading so every
// (graph) launch starts from zeros.
__device__ float g_sv[(size_t)BATCH * 64];   // sv vector accum (incl. dense)
__device__ float g_sc[BATCH];                // sum(w·x) - 0.5*sum((xV)^2) accum

// ---------------------------------------------------------------------------
// Persistent phased gather. Work unit = (group g, 16-row block). Units are
// ordered group-major; CTA c processes units c, c+G, c+2G, ... so at any
// instant the 444 CTAs span ~1.7 groups (~78 MB band) -> L2-resident window,
// each 128B line DRAM-fetched once and reused ~3.3x from L2.
// Thread layout: sub = tid/64 (0..3), t = tid%64 = k. Each thread serves rows
// sub, sub+4, sub+8, sub+12 -> 20 V gathers + 4 w gathers in flight.
// Group-0 units also fold in the dense contributions (V[:,0:13] is L1-hot).
// ---------------------------------------------------------------------------
__global__ __launch_bounds__(256) void fm_gather(const float* __restrict__ dense,
                                                 const int* __restrict__ sparse,
                                                 const float* __restrict__ w,
                                                 const float* __restrict__ V)
{
    const int tid = threadIdx.x;
    const int sub = tid >> 6;                 // 0..3
    const int t   = tid & 63;                 // k index
    const float* __restrict__ Vrow = V + (size_t)t * FLE;

    __shared__ int   cols[ROWS][8];
    __shared__ float xd[ROWS][NUM_DENSE];

    for (int unit = blockIdx.x; unit < TOTAL_UNITS; unit += GRID_GATHER) {
        const int g   = unit / UNITS_PER_GROUP;
        const int b0  = (unit % UNITS_PER_GROUP) * ROWS;
        const int gs0 = c_GS[g];
        const int ns  = c_GS[g + 1] - gs0;    // 4 or 5

        __syncthreads();                      // shared reuse across units
        if (tid < ROWS * 8) {
            int r = tid >> 3, j = tid & 7;
            if (j < ns)
                cols[r][j] = sparse[(b0 + r) * NUM_SPARSE + gs0 + j]
                           + NUM_DENSE + (gs0 + j) * FEAT_NUM;
        }
        if (g == 0 && tid < ROWS * NUM_DENSE) {
            int r = tid / NUM_DENSE, d = tid % NUM_DENSE;
            xd[r][d] = dense[(b0 + r) * NUM_DENSE + d];
        }
        __syncthreads();

        // Front-batch 24 independent loads (4 rows x (5 V + 1 w)).
        float vv[4][5], wv[4];
#pragma unroll
        for (int q = 0; q < 4; q++) {
            const int r = sub + 4 * q;
#pragma unroll
            for (int j = 0; j < 5; j++)
                vv[q][j] = (j < ns) ? __ldg(Vrow + cols[r][j]) : 0.f;
            wv[q] = (t < ns) ? __ldg(w + cols[r][t]) : 0.f;
        }

        float vd[NUM_DENSE];
        if (g == 0) {
#pragma unroll
            for (int d = 0; d < NUM_DENSE; d++) vd[d] = __ldg(Vrow + d);
        }

        float p[4];
#pragma unroll
        for (int q = 0; q < 4; q++) {
            const int r = sub + 4 * q;
            float sv = 0.f, s2 = 0.f;
#pragma unroll
            for (int j = 0; j < 5; j++) {
                sv += vv[q][j];
                s2 = fmaf(vv[q][j], vv[q][j], s2);
            }
            if (g == 0) {
#pragma unroll
                for (int d = 0; d < NUM_DENSE; d++) {
                    float xv = xd[r][d] * vd[d];
                    sv += xv;
                    s2 = fmaf(xv, xv, s2);
                }
            }
            atomicAdd(&g_sv[(size_t)(b0 + r) * 64 + t], sv);  // REDG, hidden

            p[q] = fmaf(-0.5f, s2, wv[q]);
            if (g == 0 && t < NUM_DENSE)
                p[q] += xd[r][t] * __ldg(w + t);              // L1-hot
        }

        // Interleaved 4-way warp reductions; each half-warp leader REDGs.
#pragma unroll
        for (int off = 16; off > 0; off >>= 1) {
#pragma unroll
            for (int q = 0; q < 4; q++)
                p[q] += __shfl_down_sync(0xFFFFFFFFu, p[q], off);
        }
        if ((t & 31) == 0) {
#pragma unroll
            for (int q = 0; q < 4; q++)
                atomicAdd(&g_sc[b0 + sub + 4 * q], p[q]);
        }
    }
}

// ---------------------------------------------------------------------------
// Final: warp per row. Read 64 accumulated sv values (L2-hot), square-reduce,
// add g_sc + w0, write out. Zero the accumulators for the next launch.
// ---------------------------------------------------------------------------
__global__ __launch_bounds__(256) void fm_final(const float* __restrict__ w0,
                                                float* __restrict__ out)
{
    const int lane = threadIdx.x & 31;
    const int b    = blockIdx.x * 8 + (threadIdx.x >> 5);

    float* __restrict__ svp = &g_sv[(size_t)b * 64];
    float v0 = svp[lane];
    float v1 = svp[lane + 32];
    float sc = g_sc[b];                       // issued early, used at the end
    svp[lane]      = 0.f;
    svp[lane + 32] = 0.f;

    float acc = fmaf(v0, v0, v1 * v1);
#pragma unroll
    for (int off = 16; off > 0; off >>= 1)
        acc += __shfl_down_sync(0xFFFFFFFFu, acc, off);

    if (lane == 0) {
        out[b] = __ldg(w0) + sc + 0.5f * acc;
        g_sc[b] = 0.f;
    }
}

extern "C" void kernel_launch(void* const* d_in, const int* in_sizes, int n_in,
                              void* d_out, int out_size)
{
    const float* dense  = (const float*)d_in[0];      // [4096,13] f32
    const int*   sparse = (const int*)d_in[1];        // [4096,26] int32
    const float* w0     = (const float*)d_in[2];      // [1]
    const float* w      = (const float*)d_in[3];      // [1040013]
    const float* V      = (const float*)d_in[4];      // [64,1040013]
    float*       out    = (float*)d_out;              // [4096]

    fm_gather<<<GRID_GATHER, 256>>>(dense, sparse, w, V);
    fm_final<<<BATCH / 8, 256>>>(w0, out);
}